// round 14
// baseline (speedup 1.0000x reference)
#include <cuda_runtime.h>
#include <cuda_bf16.h>
#include <cstdint>

#define BATCH 8
#define NPTS  4096
#define KNB   64
#define NS1   2048
#define NS2   512

__device__ int   g_idx1[BATCH*NS1];
__device__ float g_c1  [BATCH*NS1*3];
__device__ int   g_cnt1[BATCH*NS1];
__device__ int   g_nbr1[BATCH*NS1*KNB];
__device__ float g_x1  [BATCH*NS1*64];
__device__ int   g_idx2[BATCH*NS2];
__device__ float g_c2  [BATCH*NS2*3];
__device__ int   g_cnt2[BATCH*NS2];
__device__ int   g_nbr2[BATCH*NS2*KNB];
__device__ float g_x2  [BATCH*NS2*128];
__device__ float g_h3  [BATCH*NS2*256];
__device__ float g_part[BATCH*8*4*128];

// ---------------- packed f32x2 helpers (per-element .rn, bit-exact) -------
__device__ __forceinline__ unsigned long long pk2(float a, float b) {
    unsigned long long r;
    asm("mov.b64 %0, {%1, %2};" : "=l"(r) : "f"(a), "f"(b));
    return r;
}
__device__ __forceinline__ void upk2(unsigned long long v, float& a, float& b) {
    asm("mov.b64 {%0, %1}, %2;" : "=f"(a), "=f"(b) : "l"(v));
}
__device__ __forceinline__ unsigned long long addx2(unsigned long long a, unsigned long long b) {
    unsigned long long r;
    asm("add.rn.f32x2 %0, %1, %2;" : "=l"(r) : "l"(a), "l"(b));
    return r;
}
__device__ __forceinline__ unsigned long long mulx2(unsigned long long a, unsigned long long b) {
    unsigned long long r;
    asm("mul.rn.f32x2 %0, %1, %2;" : "=l"(r) : "l"(a), "l"(b));
    return r;
}
__device__ __forceinline__ unsigned redux_max_u32(unsigned v) {
    unsigned r;
    asm("redux.sync.max.u32 %0, %1, 0xffffffff;" : "=r"(r) : "r"(v));
    return r;
}
__device__ __forceinline__ unsigned redux_min_u32(unsigned v) {
    unsigned r;
    asm("redux.sync.min.u32 %0, %1, 0xffffffff;" : "=r"(r) : "r"(v));
    return r;
}

// ---------------- FPS body: 256 thr, redux warp-reduce, 1 barrier/iter ----
template<int NPAIR>
__device__ __forceinline__ void fps_body(
    const float* __restrict__ pb, int* __restrict__ ib,
    float* __restrict__ cb, int m_out, unsigned long long* s_keys)
{
    const int T = 256;
    int tid = threadIdx.x, lane = tid & 31, w = tid >> 5;

    unsigned long long X[NPAIR], Y[NPAIR], Z[NPAIR];
    float m0[NPAIR], m1[NPAIR];
#pragma unroll
    for (int q = 0; q < NPAIR; q++) {
        int i0 = q * (2 * T) + 2 * tid;
        const float* p0 = pb + (size_t)i0 * 3;
        X[q] = pk2(p0[0], p0[3]);
        Y[q] = pk2(p0[1], p0[4]);
        Z[q] = pk2(p0[2], p0[5]);
        m0[q] = __int_as_float(0x7f800000);
        m1[q] = __int_as_float(0x7f800000);
    }
    float cx = pb[0], cy = pb[1], cz = pb[2];
    if (tid == 0) { ib[0] = 0; cb[0] = cx; cb[1] = cy; cb[2] = cz; }

    for (int s = 1; s < m_out; s++) {
        unsigned long long CX = pk2(-cx, -cx), CY = pk2(-cy, -cy), CZ = pk2(-cz, -cz);
        float bv = -1.0f; unsigned bi = 0;
#pragma unroll
        for (int q = 0; q < NPAIR; q++) {
            unsigned long long dx = addx2(X[q], CX);
            unsigned long long dy = addx2(Y[q], CY);
            unsigned long long dz = addx2(Z[q], CZ);
            unsigned long long d2 = addx2(addx2(mulx2(dx, dx), mulx2(dy, dy)),
                                          mulx2(dz, dz));
            float d0, d1; upk2(d2, d0, d1);
            float v0 = fminf(m0[q], d0); m0[q] = v0;
            if (v0 > bv) { bv = v0; bi = (unsigned)(q * (2 * T) + 2 * tid); }
            float v1 = fminf(m1[q], d1); m1[q] = v1;
            if (v1 > bv) { bv = v1; bi = (unsigned)(q * (2 * T) + 2 * tid + 1); }
        }
        unsigned bvb = __float_as_uint(bv);
        unsigned wm  = redux_max_u32(bvb);
        unsigned cand = (bvb == wm) ? bi : 0xffffffffu;
        unsigned wi  = redux_min_u32(cand);
        unsigned long long* kb = &s_keys[(s & 1) * 8];
        if (lane == 0) kb[w] = ((unsigned long long)wm << 32) | (unsigned)(~wi);
        __syncthreads();
        unsigned long long k0 = kb[0];
#pragma unroll
        for (int j = 1; j < 8; j++) {
            unsigned long long kj = kb[j];
            if (kj > k0) k0 = kj;
        }
        unsigned win = ~(unsigned)k0;
        const float* pw = pb + (size_t)win * 3;
        cx = pw[0]; cy = pw[1]; cz = pw[2];
        if (tid == 0) {
            ib[s] = (int)win;
            cb[s*3] = cx; cb[s*3+1] = cy; cb[s*3+2] = cz;
        }
    }
}

// ---------------- ball-query body: 256 thr, exact K-nearest in radius -----
__device__ __forceinline__ void bq_body(
    const float* __restrict__ pb, int n, float r2,
    const float* __restrict__ ctr, int bm,
    int* __restrict__ nbr_out, int* __restrict__ cnt_out,
    unsigned long long* keys, int* s_cnt)
{
    int tid = threadIdx.x;
    float cx = ctr[bm*3], cy = ctr[bm*3+1], cz = ctr[bm*3+2];
    if (tid == 0) *s_cnt = 0;
    __syncthreads();
    for (int i = tid; i < n; i += 256) {
        float dx = pb[i*3] - cx, dy = pb[i*3+1] - cy, dz = pb[i*3+2] - cz;
        float d2 = __fadd_rn(__fadd_rn(__fmul_rn(dx,dx), __fmul_rn(dy,dy)),
                             __fmul_rn(dz,dz));
        if (d2 <= r2) {
            int slot = atomicAdd(s_cnt, 1);
            keys[slot] = ((unsigned long long)__float_as_uint(d2) << 32) | (unsigned)i;
        }
    }
    __syncthreads();
    int cnt = *s_cnt;
    int kk = cnt < KNB ? cnt : KNB;
    if (cnt > KNB) {
        int P2 = 1;
        while (P2 < cnt) P2 <<= 1;
        for (int i = cnt + tid; i < P2; i += 256) keys[i] = ~0ULL;
        __syncthreads();
        for (int size = 2; size <= P2; size <<= 1)
            for (int stride = size >> 1; stride > 0; stride >>= 1) {
                for (int i = tid; i < P2; i += 256) {
                    int j = i ^ stride;
                    if (j > i) {
                        unsigned long long a = keys[i], c = keys[j];
                        if ((a > c) == ((i & size) == 0)) { keys[i] = c; keys[j] = a; }
                    }
                }
                __syncthreads();
            }
    }
    for (int t = tid; t < kk; t += 256)
        nbr_out[(size_t)bm * KNB + t] = (int)(unsigned)(keys[t] & 0xffffffffu);
    if (tid == 0) cnt_out[bm] = kk;
}

// ---------------- kernel 1: FPS stage 1 -----------------------------------
__global__ __launch_bounds__(256) void fps1_kernel(const float* __restrict__ pos)
{
    __shared__ unsigned long long s_keys[16];
    int b = blockIdx.x;
    fps_body<8>(pos + (size_t)b * NPTS * 3, g_idx1 + (size_t)b * NS1,
                g_c1 + (size_t)b * NS1 * 3, NS1, s_keys);
}

// ---------------- kernel 2: fps2 (blocks 0..7) + bq1 (blocks 8..) ---------
__global__ __launch_bounds__(256) void fps2_bq1_kernel(const float* __restrict__ pos)
{
    __shared__ __align__(16) unsigned long long keys[NPTS];  // 32KB arena
    __shared__ int s_cnt;
    if (blockIdx.x < BATCH) {
        int b = blockIdx.x;
        fps_body<4>(g_c1 + (size_t)b * NS1 * 3, g_idx2 + (size_t)b * NS2,
                    g_c2 + (size_t)b * NS2 * 3, NS2, keys);
        return;
    }
    int bm = blockIdx.x - BATCH;
    int b = bm >> 11;
    bq_body(pos + (size_t)b * NPTS * 3, NPTS, 0.04f, g_c1, bm,
            g_nbr1, g_cnt1, keys, &s_cnt);
}

// ---------------- kernel 3: bq2 (blocks 0..4095) + mlp1 (blocks 4096..) ---
// mlp1 layer-2 i-vectorized (LDS.128 on s_h, stride 68).
__global__ __launch_bounds__(256) void bq2_mlp1_kernel(
    const float* __restrict__ pos,
    const float* __restrict__ w1a, const float* __restrict__ b1a,
    const float* __restrict__ w1b, const float* __restrict__ b1b)
{
    __shared__ float s_w1a[192], s_b1a[64], s_b1b[64];
    __shared__ float s_rel[192];
    __shared__ __align__(16) float s_h[64*68];   // 17.4KB; also bq2 key arena (16KB)
    __shared__ int   s_max[64];

    if (blockIdx.x < BATCH*NS2) {
        int bm = blockIdx.x;
        int b = bm >> 9;
        bq_body(g_c1 + (size_t)b * NS1 * 3, NS1, 0.16f, g_c2, bm,
                g_nbr2, g_cnt2, (unsigned long long*)s_h, &s_max[0]);
        return;
    }

    int tid = threadIdx.x;
    int bm = blockIdx.x - BATCH*NS2;
    int b = bm >> 11;
    int cnt = g_cnt1[bm];

    if (tid < 192) s_w1a[tid] = w1a[tid];
    if (tid < 64) { s_b1a[tid] = b1a[tid]; s_b1b[tid] = b1b[tid]; s_max[tid] = 0; }
    float cx = g_c1[bm*3], cy = g_c1[bm*3+1], cz = g_c1[bm*3+2];
    if (tid >= 192 && tid < 256) {
        int k = tid - 192;
        float rx = 0.f, ry = 0.f, rz = 0.f;
        if (k < cnt) {
            int nb = g_nbr1[(size_t)bm*KNB + k];
            const float* pp = pos + ((size_t)b * NPTS + nb) * 3;
            rx = pp[0] - cx; ry = pp[1] - cy; rz = pp[2] - cz;
        }
        s_rel[k*3] = rx; s_rel[k*3+1] = ry; s_rel[k*3+2] = rz;
    }
    __syncthreads();
    for (int t = tid; t < 4096; t += 256) {
        int k = t >> 6, j = t & 63;
        float v = fmaf(s_rel[k*3], s_w1a[j],
                  fmaf(s_rel[k*3+1], s_w1a[64+j],
                  fmaf(s_rel[k*3+2], s_w1a[128+j], s_b1a[j])));
        s_h[k*68 + j] = fmaxf(v, 0.f);
    }
    __syncthreads();
    int jg = tid & 15, kg = tid >> 4;
    int j0 = jg * 4, k0 = kg * 4;
    float4 bb = make_float4(s_b1b[j0], s_b1b[j0+1], s_b1b[j0+2], s_b1b[j0+3]);
    float4 a0 = bb, a1 = bb, a2 = bb, a3 = bb;
    for (int i0 = 0; i0 < 64; i0 += 4) {
        float4 f0 = *(const float4*)&s_h[(k0+0)*68 + i0];
        float4 f1 = *(const float4*)&s_h[(k0+1)*68 + i0];
        float4 f2 = *(const float4*)&s_h[(k0+2)*68 + i0];
        float4 f3 = *(const float4*)&s_h[(k0+3)*68 + i0];
#pragma unroll
        for (int u = 0; u < 4; u++) {
            float4 wv = *(const float4*)&w1b[(i0+u)*64 + j0];
            float h0 = (&f0.x)[u], h1 = (&f1.x)[u], h2 = (&f2.x)[u], h3 = (&f3.x)[u];
            a0.x = fmaf(h0,wv.x,a0.x); a0.y = fmaf(h0,wv.y,a0.y); a0.z = fmaf(h0,wv.z,a0.z); a0.w = fmaf(h0,wv.w,a0.w);
            a1.x = fmaf(h1,wv.x,a1.x); a1.y = fmaf(h1,wv.y,a1.y); a1.z = fmaf(h1,wv.z,a1.z); a1.w = fmaf(h1,wv.w,a1.w);
            a2.x = fmaf(h2,wv.x,a2.x); a2.y = fmaf(h2,wv.y,a2.y); a2.z = fmaf(h2,wv.z,a2.z); a2.w = fmaf(h2,wv.w,a2.w);
            a3.x = fmaf(h3,wv.x,a3.x); a3.y = fmaf(h3,wv.y,a3.y); a3.z = fmaf(h3,wv.z,a3.z); a3.w = fmaf(h3,wv.w,a3.w);
        }
    }
    float mx[4] = {-1.f,-1.f,-1.f,-1.f};
    if (k0   < cnt) { mx[0]=fmaxf(mx[0],a0.x); mx[1]=fmaxf(mx[1],a0.y); mx[2]=fmaxf(mx[2],a0.z); mx[3]=fmaxf(mx[3],a0.w); }
    if (k0+1 < cnt) { mx[0]=fmaxf(mx[0],a1.x); mx[1]=fmaxf(mx[1],a1.y); mx[2]=fmaxf(mx[2],a1.z); mx[3]=fmaxf(mx[3],a1.w); }
    if (k0+2 < cnt) { mx[0]=fmaxf(mx[0],a2.x); mx[1]=fmaxf(mx[1],a2.y); mx[2]=fmaxf(mx[2],a2.z); mx[3]=fmaxf(mx[3],a2.w); }
    if (k0+3 < cnt) { mx[0]=fmaxf(mx[0],a3.x); mx[1]=fmaxf(mx[1],a3.y); mx[2]=fmaxf(mx[2],a3.z); mx[3]=fmaxf(mx[3],a3.w); }
    if (k0 < cnt)
#pragma unroll
        for (int q = 0; q < 4; q++)
            atomicMax(&s_max[j0+q], __float_as_int(fmaxf(mx[q], 0.f)));
    __syncthreads();
    if (tid < 64) g_x1[(size_t)bm * 64 + tid] = __int_as_float(s_max[tid]);
}

// ---------------- SA2: feat[64,67] -> 128 relu -> 128 relu, masked max ----
// i-vectorized both layers; feat stride 68, h stride 140 (conflict-free).
__global__ __launch_bounds__(256) void mlp2_kernel(
    const float* __restrict__ w2a, const float* __restrict__ b2a,
    const float* __restrict__ w2b, const float* __restrict__ b2b)
{
    __shared__ __align__(16) float s_buf[64*140];  // feat(68) then h(140): 35.8KB
    __shared__ int   s_nbr[64];
    __shared__ int   s_max[128];
    __shared__ float s_b2a[128], s_b2b[128];

    int tid = threadIdx.x;
    int bm = blockIdx.x;
    int b = bm >> 9;
    int cnt = g_cnt2[bm];

    if (tid < 128) { s_b2a[tid] = b2a[tid]; s_b2b[tid] = b2b[tid]; s_max[tid] = 0; }
    if (tid >= 128 && tid < 192) {
        int k = tid - 128;
        s_nbr[k] = (k < cnt) ? g_nbr2[(size_t)bm*KNB + k] : 0;
    }
    float ccx = g_c2[bm*3], ccy = g_c2[bm*3+1], ccz = g_c2[bm*3+2];
    __syncthreads();
    for (int t = tid; t < 64*64; t += 256) {
        int k = t >> 6, c = t & 63;
        s_buf[k*68 + c] = (k < cnt) ? g_x1[((size_t)b*NS1 + s_nbr[k])*64 + c] : 0.f;
    }
    for (int t = tid; t < 256; t += 256) { }
    for (int t = tid; t < 192; t += 256) {
        int k = t / 3, c = t - k*3;
        float v = 0.f;
        if (k < cnt) {
            float cc = (c == 0) ? ccx : ((c == 1) ? ccy : ccz);
            v = g_c1[((size_t)b*NS1 + s_nbr[k])*3 + c] - cc;
        }
        s_buf[k*68 + 64 + c] = v;
    }
    if (tid < 64) s_buf[tid*68 + 67] = 0.f;    // pad (read by vector tail never)
    __syncthreads();

    int jg = tid & 15, kg = tid >> 4;
    int j0 = jg * 8, k0 = kg * 4;
    float4 acc[4][2];
    {   // layer 1: 67 -> 128, i-vectorized (64 in 4s + 3 scalar)
        float4 b0 = *(const float4*)&s_b2a[j0];
        float4 b1 = *(const float4*)&s_b2a[j0+4];
#pragma unroll
        for (int kk = 0; kk < 4; kk++) { acc[kk][0] = b0; acc[kk][1] = b1; }
        for (int i0 = 0; i0 < 64; i0 += 4) {
            float4 f[4];
#pragma unroll
            for (int kk = 0; kk < 4; kk++)
                f[kk] = *(const float4*)&s_buf[(k0+kk)*68 + i0];
#pragma unroll
            for (int u = 0; u < 4; u++) {
                float4 w0 = *(const float4*)&w2a[(i0+u)*128 + j0];
                float4 w1 = *(const float4*)&w2a[(i0+u)*128 + j0 + 4];
#pragma unroll
                for (int kk = 0; kk < 4; kk++) {
                    float fv = (&f[kk].x)[u];
                    acc[kk][0].x=fmaf(fv,w0.x,acc[kk][0].x); acc[kk][0].y=fmaf(fv,w0.y,acc[kk][0].y);
                    acc[kk][0].z=fmaf(fv,w0.z,acc[kk][0].z); acc[kk][0].w=fmaf(fv,w0.w,acc[kk][0].w);
                    acc[kk][1].x=fmaf(fv,w1.x,acc[kk][1].x); acc[kk][1].y=fmaf(fv,w1.y,acc[kk][1].y);
                    acc[kk][1].z=fmaf(fv,w1.z,acc[kk][1].z); acc[kk][1].w=fmaf(fv,w1.w,acc[kk][1].w);
                }
            }
        }
#pragma unroll
        for (int i = 64; i < 67; i++) {
            float4 w0 = *(const float4*)&w2a[i*128 + j0];
            float4 w1 = *(const float4*)&w2a[i*128 + j0 + 4];
#pragma unroll
            for (int kk = 0; kk < 4; kk++) {
                float fv = s_buf[(k0+kk)*68 + i];
                acc[kk][0].x=fmaf(fv,w0.x,acc[kk][0].x); acc[kk][0].y=fmaf(fv,w0.y,acc[kk][0].y);
                acc[kk][0].z=fmaf(fv,w0.z,acc[kk][0].z); acc[kk][0].w=fmaf(fv,w0.w,acc[kk][0].w);
                acc[kk][1].x=fmaf(fv,w1.x,acc[kk][1].x); acc[kk][1].y=fmaf(fv,w1.y,acc[kk][1].y);
                acc[kk][1].z=fmaf(fv,w1.z,acc[kk][1].z); acc[kk][1].w=fmaf(fv,w1.w,acc[kk][1].w);
            }
        }
    }
    __syncthreads();                           // all feat reads done
#pragma unroll
    for (int kk = 0; kk < 4; kk++) {           // relu -> h (stride 140)
        float4 r0 = make_float4(fmaxf(acc[kk][0].x,0.f), fmaxf(acc[kk][0].y,0.f),
                                fmaxf(acc[kk][0].z,0.f), fmaxf(acc[kk][0].w,0.f));
        float4 r1 = make_float4(fmaxf(acc[kk][1].x,0.f), fmaxf(acc[kk][1].y,0.f),
                                fmaxf(acc[kk][1].z,0.f), fmaxf(acc[kk][1].w,0.f));
        *(float4*)&s_buf[(k0+kk)*140 + j0]     = r0;
        *(float4*)&s_buf[(k0+kk)*140 + j0 + 4] = r1;
    }
    __syncthreads();
    {   // layer 2: 128 -> 128, i-vectorized
        float4 b0 = *(const float4*)&s_b2b[j0];
        float4 b1 = *(const float4*)&s_b2b[j0+4];
#pragma unroll
        for (int kk = 0; kk < 4; kk++) { acc[kk][0] = b0; acc[kk][1] = b1; }
        for (int i0 = 0; i0 < 128; i0 += 4) {
            float4 f[4];
#pragma unroll
            for (int kk = 0; kk < 4; kk++)
                f[kk] = *(const float4*)&s_buf[(k0+kk)*140 + i0];
#pragma unroll
            for (int u = 0; u < 4; u++) {
                float4 w0 = *(const float4*)&w2b[(i0+u)*128 + j0];
                float4 w1 = *(const float4*)&w2b[(i0+u)*128 + j0 + 4];
#pragma unroll
                for (int kk = 0; kk < 4; kk++) {
                    float fv = (&f[kk].x)[u];
                    acc[kk][0].x=fmaf(fv,w0.x,acc[kk][0].x); acc[kk][0].y=fmaf(fv,w0.y,acc[kk][0].y);
                    acc[kk][0].z=fmaf(fv,w0.z,acc[kk][0].z); acc[kk][0].w=fmaf(fv,w0.w,acc[kk][0].w);
                    acc[kk][1].x=fmaf(fv,w1.x,acc[kk][1].x); acc[kk][1].y=fmaf(fv,w1.y,acc[kk][1].y);
                    acc[kk][1].z=fmaf(fv,w1.z,acc[kk][1].z); acc[kk][1].w=fmaf(fv,w1.w,acc[kk][1].w);
                }
            }
        }
        float mx[8];
#pragma unroll
        for (int q = 0; q < 8; q++) mx[q] = -1.f;
#pragma unroll
        for (int kk = 0; kk < 4; kk++)
            if (k0 + kk < cnt) {
                mx[0]=fmaxf(mx[0],acc[kk][0].x); mx[1]=fmaxf(mx[1],acc[kk][0].y);
                mx[2]=fmaxf(mx[2],acc[kk][0].z); mx[3]=fmaxf(mx[3],acc[kk][0].w);
                mx[4]=fmaxf(mx[4],acc[kk][1].x); mx[5]=fmaxf(mx[5],acc[kk][1].y);
                mx[6]=fmaxf(mx[6],acc[kk][1].z); mx[7]=fmaxf(mx[7],acc[kk][1].w);
            }
        if (k0 < cnt)
#pragma unroll
            for (int q = 0; q < 8; q++)
                atomicMax(&s_max[j0+q], __float_as_int(fmaxf(mx[q], 0.f)));
    }
    __syncthreads();
    if (tid < 128) g_x2[(size_t)bm * 128 + tid] = __int_as_float(s_max[tid]);
}

// ---------------- Global SA layer 1: [x2,c2](131) -> 256 relu -> g_h3 -----
__global__ __launch_bounds__(256) void mlp3a_kernel(
    const float* __restrict__ w3a, const float* __restrict__ b3a)
{
    __shared__ __align__(16) float s_in[16*132];
    int tid = threadIdx.x;
    int blk = blockIdx.x;
    int b = blk >> 5;
    int g0 = (blk & 31) * 16;

    for (int t = tid; t < 16*128; t += 256) {
        int k = t >> 7, c = t & 127;
        s_in[k*132 + c] = g_x2[((size_t)b*NS2 + g0 + k)*128 + c];
    }
    if (tid < 48) {
        int k = tid / 3, c = tid - k*3;
        s_in[k*132 + 128 + c] = g_c2[((size_t)b*NS2 + g0 + k)*3 + c];
    }
    if (tid < 16) s_in[tid*132 + 131] = 0.f;   // pad
    __syncthreads();
    int jg = tid & 63, kg = tid >> 6;
    int j0 = jg * 4, k0 = kg * 4;
    float4 bb = *(const float4*)&b3a[j0];
    float4 a0 = bb, a1 = bb, a2 = bb, a3 = bb;
    for (int i0 = 0; i0 < 128; i0 += 4) {
        float4 f0 = *(const float4*)&s_in[(k0+0)*132 + i0];
        float4 f1 = *(const float4*)&s_in[(k0+1)*132 + i0];
        float4 f2 = *(const float4*)&s_in[(k0+2)*132 + i0];
        float4 f3 = *(const float4*)&s_in[(k0+3)*132 + i0];
#pragma unroll
        for (int u = 0; u < 4; u++) {
            float4 wv = *(const float4*)&w3a[(i0+u)*256 + j0];
            float h0 = (&f0.x)[u], h1 = (&f1.x)[u], h2 = (&f2.x)[u], h3 = (&f3.x)[u];
            a0.x=fmaf(h0,wv.x,a0.x); a0.y=fmaf(h0,wv.y,a0.y); a0.z=fmaf(h0,wv.z,a0.z); a0.w=fmaf(h0,wv.w,a0.w);
            a1.x=fmaf(h1,wv.x,a1.x); a1.y=fmaf(h1,wv.y,a1.y); a1.z=fmaf(h1,wv.z,a1.z); a1.w=fmaf(h1,wv.w,a1.w);
            a2.x=fmaf(h2,wv.x,a2.x); a2.y=fmaf(h2,wv.y,a2.y); a2.z=fmaf(h2,wv.z,a2.z); a2.w=fmaf(h2,wv.w,a2.w);
            a3.x=fmaf(h3,wv.x,a3.x); a3.y=fmaf(h3,wv.y,a3.y); a3.z=fmaf(h3,wv.z,a3.z); a3.w=fmaf(h3,wv.w,a3.w);
        }
    }
#pragma unroll
    for (int i = 128; i < 131; i++) {
        float4 wv = *(const float4*)&w3a[i*256 + j0];
        float h0 = s_in[k0*132+i],     h1 = s_in[(k0+1)*132+i];
        float h2 = s_in[(k0+2)*132+i], h3 = s_in[(k0+3)*132+i];
        a0.x=fmaf(h0,wv.x,a0.x); a0.y=fmaf(h0,wv.y,a0.y); a0.z=fmaf(h0,wv.z,a0.z); a0.w=fmaf(h0,wv.w,a0.w);
        a1.x=fmaf(h1,wv.x,a1.x); a1.y=fmaf(h1,wv.y,a1.y); a1.z=fmaf(h1,wv.z,a1.z); a1.w=fmaf(h1,wv.w,a1.w);
        a2.x=fmaf(h2,wv.x,a2.x); a2.y=fmaf(h2,wv.y,a2.y); a2.z=fmaf(h2,wv.z,a2.z); a2.w=fmaf(h2,wv.w,a2.w);
        a3.x=fmaf(h3,wv.x,a3.x); a3.y=fmaf(h3,wv.y,a3.y); a3.z=fmaf(h3,wv.z,a3.z); a3.w=fmaf(h3,wv.w,a3.w);
    }
    float* base = g_h3 + ((size_t)b*NS2 + g0) * 256;
    float4 r;
    r = make_float4(fmaxf(a0.x,0.f),fmaxf(a0.y,0.f),fmaxf(a0.z,0.f),fmaxf(a0.w,0.f));
    *(float4*)&base[(k0+0)*256 + j0] = r;
    r = make_float4(fmaxf(a1.x,0.f),fmaxf(a1.y,0.f),fmaxf(a1.z,0.f),fmaxf(a1.w,0.f));
    *(float4*)&base[(k0+1)*256 + j0] = r;
    r = make_float4(fmaxf(a2.x,0.f),fmaxf(a2.y,0.f),fmaxf(a2.z,0.f),fmaxf(a2.w,0.f));
    *(float4*)&base[(k0+2)*256 + j0] = r;
    r = make_float4(fmaxf(a3.x,0.f),fmaxf(a3.y,0.f),fmaxf(a3.z,0.f),fmaxf(a3.w,0.f));
    *(float4*)&base[(k0+3)*256 + j0] = r;
}

// ---------------- Global SA layer 2: 256 -> 1024, max over rows -----------
__global__ __launch_bounds__(256) void mlp3b_kernel(const float* __restrict__ w3b)
{
    __shared__ float s_red[8*128];
    int tid = threadIdx.x;
    int rb = blockIdx.x, cb = blockIdx.y, b = blockIdx.z;
    int jg = tid & 31, kg = tid >> 5;
    int j0 = jg * 4;

    float mx[4] = {-3.4e38f, -3.4e38f, -3.4e38f, -3.4e38f};
    for (int t = 0; t < 16; t++) {
        int r = rb * 128 + kg + 8 * t;
        const float* hr = g_h3 + ((size_t)b*NS2 + r) * 256;
        float4 acc = make_float4(0.f, 0.f, 0.f, 0.f);
        for (int i0 = 0; i0 < 256; i0 += 4) {
            float4 fh = *(const float4*)&hr[i0];
#pragma unroll
            for (int u = 0; u < 4; u++) {
                float f = (&fh.x)[u];
                float4 wv = *(const float4*)&w3b[(size_t)(i0+u)*1024 + cb*128 + j0];
                acc.x=fmaf(f,wv.x,acc.x); acc.y=fmaf(f,wv.y,acc.y);
                acc.z=fmaf(f,wv.z,acc.z); acc.w=fmaf(f,wv.w,acc.w);
            }
        }
        mx[0]=fmaxf(mx[0],acc.x); mx[1]=fmaxf(mx[1],acc.y);
        mx[2]=fmaxf(mx[2],acc.z); mx[3]=fmaxf(mx[3],acc.w);
    }
#pragma unroll
    for (int q = 0; q < 4; q++) s_red[kg*128 + j0 + q] = mx[q];
    __syncthreads();
    if (tid < 32) {
        int j = tid * 4;
#pragma unroll
        for (int q = 0; q < 4; q++) {
            float v = s_red[j+q];
            for (int k = 1; k < 8; k++) v = fmaxf(v, s_red[k*128 + j + q]);
            g_part[(((size_t)b*8 + cb)*4 + rb)*128 + j + q] = v;
        }
    }
}

__global__ __launch_bounds__(1024) void fin_kernel(
    const float* __restrict__ b3b, float* __restrict__ out)
{
    int c = threadIdx.x, b = blockIdx.x;
    int cb = c >> 7, j = c & 127;
    float v = -3.4e38f;
    for (int rb = 0; rb < 4; rb++)
        v = fmaxf(v, g_part[(((size_t)b*8 + cb)*4 + rb)*128 + j]);
    out[(size_t)b*1024 + c] = __fadd_rn(v, b3b[c]);
}

// ---------------- launcher: kernel launches ONLY --------------------------
extern "C" void kernel_launch(void* const* d_in, const int* in_sizes, int n_in,
                              void* d_out, int out_size)
{
    const float* pos = (const float*)d_in[0];
    const float* w1a = (const float*)d_in[1];
    const float* b1a = (const float*)d_in[2];
    const float* w1b = (const float*)d_in[3];
    const float* b1b = (const float*)d_in[4];
    const float* w2a = (const float*)d_in[5];
    const float* b2a = (const float*)d_in[6];
    const float* w2b = (const float*)d_in[7];
    const float* b2b = (const float*)d_in[8];
    const float* w3a = (const float*)d_in[9];
    const float* b3a = (const float*)d_in[10];
    const float* w3b = (const float*)d_in[11];
    const float* b3b = (const float*)d_in[12];
    float* out = (float*)d_out;

    fps1_kernel<<<BATCH, 256>>>(pos);
    fps2_bq1_kernel<<<BATCH + BATCH*NS1, 256>>>(pos);
    bq2_mlp1_kernel<<<BATCH*NS2 + BATCH*NS1, 256>>>(pos, w1a, b1a, w1b, b1b);
    mlp2_kernel<<<BATCH*NS2, 256>>>(w2a, b2a, w2b, b2b);
    mlp3a_kernel<<<BATCH*32, 256>>>(w3a, b3a);
    mlp3b_kernel<<<dim3(4, 8, BATCH), 256>>>(w3b);
    fin_kernel<<<BATCH, 1024>>>(b3b, out);
    (void)in_sizes; (void)n_in; (void)out_size;
}

// round 15
// speedup vs baseline: 1.0286x; 1.0286x over previous
#include <cuda_runtime.h>
#include <cuda_bf16.h>
#include <cstdint>

#define BATCH 8
#define NPTS  4096
#define KNB   64
#define NS1   2048
#define NS2   512

__device__ int   g_idx1[BATCH*NS1];
__device__ float g_c1  [BATCH*NS1*3];
__device__ int   g_cnt1[BATCH*NS1];
__device__ int   g_nbr1[BATCH*NS1*KNB];
__device__ float g_x1  [BATCH*NS1*64];
__device__ int   g_idx2[BATCH*NS2];
__device__ float g_c2  [BATCH*NS2*3];
__device__ int   g_cnt2[BATCH*NS2];
__device__ int   g_nbr2[BATCH*NS2*KNB];
__device__ float g_x2  [BATCH*NS2*128];
__device__ float g_h3  [BATCH*NS2*256];
__device__ float g_part[BATCH*8*4*128];

// ---------------- packed f32x2 helpers (per-element .rn, bit-exact) -------
__device__ __forceinline__ unsigned long long pk2(float a, float b) {
    unsigned long long r;
    asm("mov.b64 %0, {%1, %2};" : "=l"(r) : "f"(a), "f"(b));
    return r;
}
__device__ __forceinline__ void upk2(unsigned long long v, float& a, float& b) {
    asm("mov.b64 {%0, %1}, %2;" : "=f"(a), "=f"(b) : "l"(v));
}
__device__ __forceinline__ unsigned long long addx2(unsigned long long a, unsigned long long b) {
    unsigned long long r;
    asm("add.rn.f32x2 %0, %1, %2;" : "=l"(r) : "l"(a), "l"(b));
    return r;
}
__device__ __forceinline__ unsigned long long mulx2(unsigned long long a, unsigned long long b) {
    unsigned long long r;
    asm("mul.rn.f32x2 %0, %1, %2;" : "=l"(r) : "l"(a), "l"(b));
    return r;
}
__device__ __forceinline__ unsigned redux_max_u32(unsigned v) {
    unsigned r;
    asm("redux.sync.max.u32 %0, %1, 0xffffffff;" : "=r"(r) : "r"(v));
    return r;
}
__device__ __forceinline__ unsigned redux_min_u32(unsigned v) {
    unsigned r;
    asm("redux.sync.min.u32 %0, %1, 0xffffffff;" : "=r"(r) : "r"(v));
    return r;
}

// ---------------- FPS body: 256 thr, redux warp-reduce, 1 barrier/iter ----
template<int NPAIR>
__device__ __forceinline__ void fps_body(
    const float* __restrict__ pb, int* __restrict__ ib,
    float* __restrict__ cb, int m_out, unsigned long long* s_keys)
{
    const int T = 256;
    int tid = threadIdx.x, lane = tid & 31, w = tid >> 5;

    unsigned long long X[NPAIR], Y[NPAIR], Z[NPAIR];
    float m0[NPAIR], m1[NPAIR];
#pragma unroll
    for (int q = 0; q < NPAIR; q++) {
        int i0 = q * (2 * T) + 2 * tid;
        const float* p0 = pb + (size_t)i0 * 3;
        X[q] = pk2(p0[0], p0[3]);
        Y[q] = pk2(p0[1], p0[4]);
        Z[q] = pk2(p0[2], p0[5]);
        m0[q] = __int_as_float(0x7f800000);
        m1[q] = __int_as_float(0x7f800000);
    }
    float cx = pb[0], cy = pb[1], cz = pb[2];
    if (tid == 0) { ib[0] = 0; cb[0] = cx; cb[1] = cy; cb[2] = cz; }

    for (int s = 1; s < m_out; s++) {
        unsigned long long CX = pk2(-cx, -cx), CY = pk2(-cy, -cy), CZ = pk2(-cz, -cz);
        float bv = -1.0f; unsigned bi = 0;
#pragma unroll
        for (int q = 0; q < NPAIR; q++) {
            unsigned long long dx = addx2(X[q], CX);
            unsigned long long dy = addx2(Y[q], CY);
            unsigned long long dz = addx2(Z[q], CZ);
            unsigned long long d2 = addx2(addx2(mulx2(dx, dx), mulx2(dy, dy)),
                                          mulx2(dz, dz));
            float d0, d1; upk2(d2, d0, d1);
            float v0 = fminf(m0[q], d0); m0[q] = v0;
            if (v0 > bv) { bv = v0; bi = (unsigned)(q * (2 * T) + 2 * tid); }
            float v1 = fminf(m1[q], d1); m1[q] = v1;
            if (v1 > bv) { bv = v1; bi = (unsigned)(q * (2 * T) + 2 * tid + 1); }
        }
        unsigned bvb = __float_as_uint(bv);
        unsigned wm  = redux_max_u32(bvb);
        unsigned cand = (bvb == wm) ? bi : 0xffffffffu;
        unsigned wi  = redux_min_u32(cand);
        unsigned long long* kb = &s_keys[(s & 1) * 8];
        if (lane == 0) kb[w] = ((unsigned long long)wm << 32) | (unsigned)(~wi);
        __syncthreads();
        unsigned long long k0 = kb[0];
#pragma unroll
        for (int j = 1; j < 8; j++) {
            unsigned long long kj = kb[j];
            if (kj > k0) k0 = kj;
        }
        unsigned win = ~(unsigned)k0;
        const float* pw = pb + (size_t)win * 3;
        cx = pw[0]; cy = pw[1]; cz = pw[2];
        if (tid == 0) {
            ib[s] = (int)win;
            cb[s*3] = cx; cb[s*3+1] = cy; cb[s*3+2] = cz;
        }
    }
}

// ---------------- ball-query body: 256 thr, exact K-nearest in radius -----
__device__ __forceinline__ void bq_body(
    const float* __restrict__ pb, int n, float r2,
    const float* __restrict__ ctr, int bm,
    int* __restrict__ nbr_out, int* __restrict__ cnt_out,
    unsigned long long* keys, int* s_cnt)
{
    int tid = threadIdx.x;
    float cx = ctr[bm*3], cy = ctr[bm*3+1], cz = ctr[bm*3+2];
    if (tid == 0) *s_cnt = 0;
    __syncthreads();
    for (int i = tid; i < n; i += 256) {
        float dx = pb[i*3] - cx, dy = pb[i*3+1] - cy, dz = pb[i*3+2] - cz;
        float d2 = __fadd_rn(__fadd_rn(__fmul_rn(dx,dx), __fmul_rn(dy,dy)),
                             __fmul_rn(dz,dz));
        if (d2 <= r2) {
            int slot = atomicAdd(s_cnt, 1);
            keys[slot] = ((unsigned long long)__float_as_uint(d2) << 32) | (unsigned)i;
        }
    }
    __syncthreads();
    int cnt = *s_cnt;
    int kk = cnt < KNB ? cnt : KNB;
    if (cnt > KNB) {
        int P2 = 1;
        while (P2 < cnt) P2 <<= 1;
        for (int i = cnt + tid; i < P2; i += 256) keys[i] = ~0ULL;
        __syncthreads();
        for (int size = 2; size <= P2; size <<= 1)
            for (int stride = size >> 1; stride > 0; stride >>= 1) {
                for (int i = tid; i < P2; i += 256) {
                    int j = i ^ stride;
                    if (j > i) {
                        unsigned long long a = keys[i], c = keys[j];
                        if ((a > c) == ((i & size) == 0)) { keys[i] = c; keys[j] = a; }
                    }
                }
                __syncthreads();
            }
    }
    for (int t = tid; t < kk; t += 256)
        nbr_out[(size_t)bm * KNB + t] = (int)(unsigned)(keys[t] & 0xffffffffu);
    if (tid == 0) cnt_out[bm] = kk;
}

// ---------------- kernel 1: FPS stage 1 -----------------------------------
__global__ __launch_bounds__(256) void fps1_kernel(const float* __restrict__ pos)
{
    __shared__ unsigned long long s_keys[16];
    int b = blockIdx.x;
    fps_body<8>(pos + (size_t)b * NPTS * 3, g_idx1 + (size_t)b * NS1,
                g_c1 + (size_t)b * NS1 * 3, NS1, s_keys);
}

// ---------------- kernel 2: fps2 (blocks 0..7) + bq1 (blocks 8..) ---------
__global__ __launch_bounds__(256) void fps2_bq1_kernel(const float* __restrict__ pos)
{
    __shared__ __align__(16) unsigned long long keys[NPTS];  // 32KB arena
    __shared__ int s_cnt;
    if (blockIdx.x < BATCH) {
        int b = blockIdx.x;
        fps_body<4>(g_c1 + (size_t)b * NS1 * 3, g_idx2 + (size_t)b * NS2,
                    g_c2 + (size_t)b * NS2 * 3, NS2, keys);
        return;
    }
    int bm = blockIdx.x - BATCH;
    int b = bm >> 11;
    bq_body(pos + (size_t)b * NPTS * 3, NPTS, 0.04f, g_c1, bm,
            g_nbr1, g_cnt1, keys, &s_cnt);
}

// ---------------- kernel 3: bq2 (blocks 0..4095) + mlp1 (blocks 4096..) ---
// (R13 version: scalar layer-2, s_h stride 65)
__global__ __launch_bounds__(256) void bq2_mlp1_kernel(
    const float* __restrict__ pos,
    const float* __restrict__ w1a, const float* __restrict__ b1a,
    const float* __restrict__ w1b, const float* __restrict__ b1b)
{
    __shared__ float s_w1a[192], s_b1a[64], s_b1b[64];
    __shared__ float s_rel[192];
    __shared__ __align__(16) float s_h[64*65];   // also bq2 key arena (16KB)
    __shared__ int   s_max[64];

    if (blockIdx.x < BATCH*NS2) {
        int bm = blockIdx.x;
        int b = bm >> 9;
        bq_body(g_c1 + (size_t)b * NS1 * 3, NS1, 0.16f, g_c2, bm,
                g_nbr2, g_cnt2, (unsigned long long*)s_h, &s_max[0]);
        return;
    }

    int tid = threadIdx.x;
    int bm = blockIdx.x - BATCH*NS2;
    int b = bm >> 11;
    int cnt = g_cnt1[bm];

    if (tid < 192) s_w1a[tid] = w1a[tid];
    if (tid < 64) { s_b1a[tid] = b1a[tid]; s_b1b[tid] = b1b[tid]; s_max[tid] = 0; }
    float cx = g_c1[bm*3], cy = g_c1[bm*3+1], cz = g_c1[bm*3+2];
    if (tid >= 192 && tid < 256) {
        int k = tid - 192;
        float rx = 0.f, ry = 0.f, rz = 0.f;
        if (k < cnt) {
            int nb = g_nbr1[(size_t)bm*KNB + k];
            const float* pp = pos + ((size_t)b * NPTS + nb) * 3;
            rx = pp[0] - cx; ry = pp[1] - cy; rz = pp[2] - cz;
        }
        s_rel[k*3] = rx; s_rel[k*3+1] = ry; s_rel[k*3+2] = rz;
    }
    __syncthreads();
    for (int t = tid; t < 4096; t += 256) {
        int k = t >> 6, j = t & 63;
        float v = fmaf(s_rel[k*3], s_w1a[j],
                  fmaf(s_rel[k*3+1], s_w1a[64+j],
                  fmaf(s_rel[k*3+2], s_w1a[128+j], s_b1a[j])));
        s_h[k*65 + j] = fmaxf(v, 0.f);
    }
    __syncthreads();
    int jg = tid & 15, kg = tid >> 4;
    int j0 = jg * 4, k0 = kg * 4;
    float4 bb = make_float4(s_b1b[j0], s_b1b[j0+1], s_b1b[j0+2], s_b1b[j0+3]);
    float4 a0 = bb, a1 = bb, a2 = bb, a3 = bb;
#pragma unroll 8
    for (int i = 0; i < 64; i++) {
        float4 wv = *(const float4*)&w1b[i*64 + j0];
        float h0 = s_h[k0*65+i], h1 = s_h[(k0+1)*65+i];
        float h2 = s_h[(k0+2)*65+i], h3 = s_h[(k0+3)*65+i];
        a0.x = fmaf(h0,wv.x,a0.x); a0.y = fmaf(h0,wv.y,a0.y); a0.z = fmaf(h0,wv.z,a0.z); a0.w = fmaf(h0,wv.w,a0.w);
        a1.x = fmaf(h1,wv.x,a1.x); a1.y = fmaf(h1,wv.y,a1.y); a1.z = fmaf(h1,wv.z,a1.z); a1.w = fmaf(h1,wv.w,a1.w);
        a2.x = fmaf(h2,wv.x,a2.x); a2.y = fmaf(h2,wv.y,a2.y); a2.z = fmaf(h2,wv.z,a2.z); a2.w = fmaf(h2,wv.w,a2.w);
        a3.x = fmaf(h3,wv.x,a3.x); a3.y = fmaf(h3,wv.y,a3.y); a3.z = fmaf(h3,wv.z,a3.z); a3.w = fmaf(h3,wv.w,a3.w);
    }
    float mx[4] = {-1.f,-1.f,-1.f,-1.f};
    if (k0   < cnt) { mx[0]=fmaxf(mx[0],a0.x); mx[1]=fmaxf(mx[1],a0.y); mx[2]=fmaxf(mx[2],a0.z); mx[3]=fmaxf(mx[3],a0.w); }
    if (k0+1 < cnt) { mx[0]=fmaxf(mx[0],a1.x); mx[1]=fmaxf(mx[1],a1.y); mx[2]=fmaxf(mx[2],a1.z); mx[3]=fmaxf(mx[3],a1.w); }
    if (k0+2 < cnt) { mx[0]=fmaxf(mx[0],a2.x); mx[1]=fmaxf(mx[1],a2.y); mx[2]=fmaxf(mx[2],a2.z); mx[3]=fmaxf(mx[3],a2.w); }
    if (k0+3 < cnt) { mx[0]=fmaxf(mx[0],a3.x); mx[1]=fmaxf(mx[1],a3.y); mx[2]=fmaxf(mx[2],a3.z); mx[3]=fmaxf(mx[3],a3.w); }
    if (k0 < cnt)
#pragma unroll
        for (int q = 0; q < 4; q++)
            atomicMax(&s_max[j0+q], __float_as_int(fmaxf(mx[q], 0.f)));
    __syncthreads();
    if (tid < 64) g_x1[(size_t)bm * 64 + tid] = __int_as_float(s_max[tid]);
}

// ---------------- SA2: feat[64,67] -> 128 relu -> 128 relu, masked max ----
// 2-i unroll with float2 activation loads: 4 L1 instr / 32 FMA, ~60 regs.
// feat stride 68 (8B-aligned float2), h stride 132 (as R13).
__global__ __launch_bounds__(256) void mlp2_kernel(
    const float* __restrict__ w2a, const float* __restrict__ b2a,
    const float* __restrict__ w2b, const float* __restrict__ b2b)
{
    __shared__ __align__(16) float s_buf[64*132];  // feat(68) then h(132): 33.8KB
    __shared__ int   s_nbr[64];
    __shared__ int   s_max[128];
    __shared__ float s_b2a[128], s_b2b[128];

    int tid = threadIdx.x;
    int bm = blockIdx.x;
    int b = bm >> 9;
    int cnt = g_cnt2[bm];

    if (tid < 128) { s_b2a[tid] = b2a[tid]; s_b2b[tid] = b2b[tid]; s_max[tid] = 0; }
    if (tid >= 128 && tid < 192) {
        int k = tid - 128;
        s_nbr[k] = (k < cnt) ? g_nbr2[(size_t)bm*KNB + k] : 0;
    }
    float ccx = g_c2[bm*3], ccy = g_c2[bm*3+1], ccz = g_c2[bm*3+2];
    __syncthreads();
    for (int t = tid; t < 64*64; t += 256) {
        int k = t >> 6, c = t & 63;
        s_buf[k*68 + c] = (k < cnt) ? g_x1[((size_t)b*NS1 + s_nbr[k])*64 + c] : 0.f;
    }
    for (int t = tid; t < 192; t += 256) {
        int k = t / 3, c = t - k*3;
        float v = 0.f;
        if (k < cnt) {
            float cc = (c == 0) ? ccx : ((c == 1) ? ccy : ccz);
            v = g_c1[((size_t)b*NS1 + s_nbr[k])*3 + c] - cc;
        }
        s_buf[k*68 + 64 + c] = v;
    }
    if (tid < 64) s_buf[tid*68 + 67] = 0.f;    // pad
    __syncthreads();

    int jg = tid & 15, kg = tid >> 4;
    int j0 = jg * 8, k0 = kg * 4;
    float4 acc[4][2];
    {   // layer 1: 67 -> 128, 2-i unroll (66 in pairs + 1 scalar)
        float4 b0 = *(const float4*)&s_b2a[j0];
        float4 b1 = *(const float4*)&s_b2a[j0+4];
#pragma unroll
        for (int kk = 0; kk < 4; kk++) { acc[kk][0] = b0; acc[kk][1] = b1; }
        for (int i0 = 0; i0 < 66; i0 += 2) {
            float2 f0 = *(const float2*)&s_buf[(k0+0)*68 + i0];
            float2 f1 = *(const float2*)&s_buf[(k0+1)*68 + i0];
            float2 f2 = *(const float2*)&s_buf[(k0+2)*68 + i0];
            float2 f3 = *(const float2*)&s_buf[(k0+3)*68 + i0];
#pragma unroll
            for (int u = 0; u < 2; u++) {
                float4 w0 = *(const float4*)&w2a[(i0+u)*128 + j0];
                float4 w1 = *(const float4*)&w2a[(i0+u)*128 + j0 + 4];
                float v0 = u ? f0.y : f0.x, v1 = u ? f1.y : f1.x;
                float v2 = u ? f2.y : f2.x, v3 = u ? f3.y : f3.x;
                acc[0][0].x=fmaf(v0,w0.x,acc[0][0].x); acc[0][0].y=fmaf(v0,w0.y,acc[0][0].y);
                acc[0][0].z=fmaf(v0,w0.z,acc[0][0].z); acc[0][0].w=fmaf(v0,w0.w,acc[0][0].w);
                acc[0][1].x=fmaf(v0,w1.x,acc[0][1].x); acc[0][1].y=fmaf(v0,w1.y,acc[0][1].y);
                acc[0][1].z=fmaf(v0,w1.z,acc[0][1].z); acc[0][1].w=fmaf(v0,w1.w,acc[0][1].w);
                acc[1][0].x=fmaf(v1,w0.x,acc[1][0].x); acc[1][0].y=fmaf(v1,w0.y,acc[1][0].y);
                acc[1][0].z=fmaf(v1,w0.z,acc[1][0].z); acc[1][0].w=fmaf(v1,w0.w,acc[1][0].w);
                acc[1][1].x=fmaf(v1,w1.x,acc[1][1].x); acc[1][1].y=fmaf(v1,w1.y,acc[1][1].y);
                acc[1][1].z=fmaf(v1,w1.z,acc[1][1].z); acc[1][1].w=fmaf(v1,w1.w,acc[1][1].w);
                acc[2][0].x=fmaf(v2,w0.x,acc[2][0].x); acc[2][0].y=fmaf(v2,w0.y,acc[2][0].y);
                acc[2][0].z=fmaf(v2,w0.z,acc[2][0].z); acc[2][0].w=fmaf(v2,w0.w,acc[2][0].w);
                acc[2][1].x=fmaf(v2,w1.x,acc[2][1].x); acc[2][1].y=fmaf(v2,w1.y,acc[2][1].y);
                acc[2][1].z=fmaf(v2,w1.z,acc[2][1].z); acc[2][1].w=fmaf(v2,w1.w,acc[2][1].w);
                acc[3][0].x=fmaf(v3,w0.x,acc[3][0].x); acc[3][0].y=fmaf(v3,w0.y,acc[3][0].y);
                acc[3][0].z=fmaf(v3,w0.z,acc[3][0].z); acc[3][0].w=fmaf(v3,w0.w,acc[3][0].w);
                acc[3][1].x=fmaf(v3,w1.x,acc[3][1].x); acc[3][1].y=fmaf(v3,w1.y,acc[3][1].y);
                acc[3][1].z=fmaf(v3,w1.z,acc[3][1].z); acc[3][1].w=fmaf(v3,w1.w,acc[3][1].w);
            }
        }
        {   // tail i = 66
            const int i = 66;
            float4 w0 = *(const float4*)&w2a[i*128 + j0];
            float4 w1 = *(const float4*)&w2a[i*128 + j0 + 4];
#pragma unroll
            for (int kk = 0; kk < 4; kk++) {
                float fv = s_buf[(k0+kk)*68 + i];
                acc[kk][0].x=fmaf(fv,w0.x,acc[kk][0].x); acc[kk][0].y=fmaf(fv,w0.y,acc[kk][0].y);
                acc[kk][0].z=fmaf(fv,w0.z,acc[kk][0].z); acc[kk][0].w=fmaf(fv,w0.w,acc[kk][0].w);
                acc[kk][1].x=fmaf(fv,w1.x,acc[kk][1].x); acc[kk][1].y=fmaf(fv,w1.y,acc[kk][1].y);
                acc[kk][1].z=fmaf(fv,w1.z,acc[kk][1].z); acc[kk][1].w=fmaf(fv,w1.w,acc[kk][1].w);
            }
        }
    }
    __syncthreads();                           // all feat reads done
#pragma unroll
    for (int kk = 0; kk < 4; kk++) {           // relu -> h (stride 132)
        float4 r0 = make_float4(fmaxf(acc[kk][0].x,0.f), fmaxf(acc[kk][0].y,0.f),
                                fmaxf(acc[kk][0].z,0.f), fmaxf(acc[kk][0].w,0.f));
        float4 r1 = make_float4(fmaxf(acc[kk][1].x,0.f), fmaxf(acc[kk][1].y,0.f),
                                fmaxf(acc[kk][1].z,0.f), fmaxf(acc[kk][1].w,0.f));
        *(float4*)&s_buf[(k0+kk)*132 + j0]     = r0;
        *(float4*)&s_buf[(k0+kk)*132 + j0 + 4] = r1;
    }
    __syncthreads();
    {   // layer 2: 128 -> 128, 2-i unroll with float2 loads
        float4 b0 = *(const float4*)&s_b2b[j0];
        float4 b1 = *(const float4*)&s_b2b[j0+4];
#pragma unroll
        for (int kk = 0; kk < 4; kk++) { acc[kk][0] = b0; acc[kk][1] = b1; }
        for (int i0 = 0; i0 < 128; i0 += 2) {
            float2 f0 = *(const float2*)&s_buf[(k0+0)*132 + i0];
            float2 f1 = *(const float2*)&s_buf[(k0+1)*132 + i0];
            float2 f2 = *(const float2*)&s_buf[(k0+2)*132 + i0];
            float2 f3 = *(const float2*)&s_buf[(k0+3)*132 + i0];
#pragma unroll
            for (int u = 0; u < 2; u++) {
                float4 w0 = *(const float4*)&w2b[(i0+u)*128 + j0];
                float4 w1 = *(const float4*)&w2b[(i0+u)*128 + j0 + 4];
                float v0 = u ? f0.y : f0.x, v1 = u ? f1.y : f1.x;
                float v2 = u ? f2.y : f2.x, v3 = u ? f3.y : f3.x;
                acc[0][0].x=fmaf(v0,w0.x,acc[0][0].x); acc[0][0].y=fmaf(v0,w0.y,acc[0][0].y);
                acc[0][0].z=fmaf(v0,w0.z,acc[0][0].z); acc[0][0].w=fmaf(v0,w0.w,acc[0][0].w);
                acc[0][1].x=fmaf(v0,w1.x,acc[0][1].x); acc[0][1].y=fmaf(v0,w1.y,acc[0][1].y);
                acc[0][1].z=fmaf(v0,w1.z,acc[0][1].z); acc[0][1].w=fmaf(v0,w1.w,acc[0][1].w);
                acc[1][0].x=fmaf(v1,w0.x,acc[1][0].x); acc[1][0].y=fmaf(v1,w0.y,acc[1][0].y);
                acc[1][0].z=fmaf(v1,w0.z,acc[1][0].z); acc[1][0].w=fmaf(v1,w0.w,acc[1][0].w);
                acc[1][1].x=fmaf(v1,w1.x,acc[1][1].x); acc[1][1].y=fmaf(v1,w1.y,acc[1][1].y);
                acc[1][1].z=fmaf(v1,w1.z,acc[1][1].z); acc[1][1].w=fmaf(v1,w1.w,acc[1][1].w);
                acc[2][0].x=fmaf(v2,w0.x,acc[2][0].x); acc[2][0].y=fmaf(v2,w0.y,acc[2][0].y);
                acc[2][0].z=fmaf(v2,w0.z,acc[2][0].z); acc[2][0].w=fmaf(v2,w0.w,acc[2][0].w);
                acc[2][1].x=fmaf(v2,w1.x,acc[2][1].x); acc[2][1].y=fmaf(v2,w1.y,acc[2][1].y);
                acc[2][1].z=fmaf(v2,w1.z,acc[2][1].z); acc[2][1].w=fmaf(v2,w1.w,acc[2][1].w);
                acc[3][0].x=fmaf(v3,w0.x,acc[3][0].x); acc[3][0].y=fmaf(v3,w0.y,acc[3][0].y);
                acc[3][0].z=fmaf(v3,w0.z,acc[3][0].z); acc[3][0].w=fmaf(v3,w0.w,acc[3][0].w);
                acc[3][1].x=fmaf(v3,w1.x,acc[3][1].x); acc[3][1].y=fmaf(v3,w1.y,acc[3][1].y);
                acc[3][1].z=fmaf(v3,w1.z,acc[3][1].z); acc[3][1].w=fmaf(v3,w1.w,acc[3][1].w);
            }
        }
        float mx[8];
#pragma unroll
        for (int q = 0; q < 8; q++) mx[q] = -1.f;
#pragma unroll
        for (int kk = 0; kk < 4; kk++)
            if (k0 + kk < cnt) {
                mx[0]=fmaxf(mx[0],acc[kk][0].x); mx[1]=fmaxf(mx[1],acc[kk][0].y);
                mx[2]=fmaxf(mx[2],acc[kk][0].z); mx[3]=fmaxf(mx[3],acc[kk][0].w);
                mx[4]=fmaxf(mx[4],acc[kk][1].x); mx[5]=fmaxf(mx[5],acc[kk][1].y);
                mx[6]=fmaxf(mx[6],acc[kk][1].z); mx[7]=fmaxf(mx[7],acc[kk][1].w);
            }
        if (k0 < cnt)
#pragma unroll
            for (int q = 0; q < 8; q++)
                atomicMax(&s_max[j0+q], __float_as_int(fmaxf(mx[q], 0.f)));
    }
    __syncthreads();
    if (tid < 128) g_x2[(size_t)bm * 128 + tid] = __int_as_float(s_max[tid]);
}

// ---------------- Global SA layer 1: [x2,c2](131) -> 256 relu -> g_h3 -----
__global__ __launch_bounds__(256) void mlp3a_kernel(
    const float* __restrict__ w3a, const float* __restrict__ b3a)
{
    __shared__ float s_in[16*132];
    int tid = threadIdx.x;
    int blk = blockIdx.x;
    int b = blk >> 5;
    int g0 = (blk & 31) * 16;

    for (int t = tid; t < 16*128; t += 256) {
        int k = t >> 7, c = t & 127;
        s_in[k*132 + c] = g_x2[((size_t)b*NS2 + g0 + k)*128 + c];
    }
    if (tid < 48) {
        int k = tid / 3, c = tid - k*3;
        s_in[k*132 + 128 + c] = g_c2[((size_t)b*NS2 + g0 + k)*3 + c];
    }
    __syncthreads();
    int jg = tid & 63, kg = tid >> 6;
    int j0 = jg * 4, k0 = kg * 4;
    float4 bb = *(const float4*)&b3a[j0];
    float4 a0 = bb, a1 = bb, a2 = bb, a3 = bb;
    for (int i = 0; i < 131; i++) {
        float4 wv = *(const float4*)&w3a[i*256 + j0];
        float f0 = s_in[k0*132+i],     f1 = s_in[(k0+1)*132+i];
        float f2 = s_in[(k0+2)*132+i], f3 = s_in[(k0+3)*132+i];
        a0.x=fmaf(f0,wv.x,a0.x); a0.y=fmaf(f0,wv.y,a0.y); a0.z=fmaf(f0,wv.z,a0.z); a0.w=fmaf(f0,wv.w,a0.w);
        a1.x=fmaf(f1,wv.x,a1.x); a1.y=fmaf(f1,wv.y,a1.y); a1.z=fmaf(f1,wv.z,a1.z); a1.w=fmaf(f1,wv.w,a1.w);
        a2.x=fmaf(f2,wv.x,a2.x); a2.y=fmaf(f2,wv.y,a2.y); a2.z=fmaf(f2,wv.z,a2.z); a2.w=fmaf(f2,wv.w,a2.w);
        a3.x=fmaf(f3,wv.x,a3.x); a3.y=fmaf(f3,wv.y,a3.y); a3.z=fmaf(f3,wv.z,a3.z); a3.w=fmaf(f3,wv.w,a3.w);
    }
    float* base = g_h3 + ((size_t)b*NS2 + g0) * 256;
    float4 r;
    r = make_float4(fmaxf(a0.x,0.f),fmaxf(a0.y,0.f),fmaxf(a0.z,0.f),fmaxf(a0.w,0.f));
    *(float4*)&base[(k0+0)*256 + j0] = r;
    r = make_float4(fmaxf(a1.x,0.f),fmaxf(a1.y,0.f),fmaxf(a1.z,0.f),fmaxf(a1.w,0.f));
    *(float4*)&base[(k0+1)*256 + j0] = r;
    r = make_float4(fmaxf(a2.x,0.f),fmaxf(a2.y,0.f),fmaxf(a2.z,0.f),fmaxf(a2.w,0.f));
    *(float4*)&base[(k0+2)*256 + j0] = r;
    r = make_float4(fmaxf(a3.x,0.f),fmaxf(a3.y,0.f),fmaxf(a3.z,0.f),fmaxf(a3.w,0.f));
    *(float4*)&base[(k0+3)*256 + j0] = r;
}

// ---------------- Global SA layer 2: 256 -> 1024, max over rows -----------
__global__ __launch_bounds__(256) void mlp3b_kernel(const float* __restrict__ w3b)
{
    __shared__ float s_red[8*128];
    int tid = threadIdx.x;
    int rb = blockIdx.x, cb = blockIdx.y, b = blockIdx.z;
    int jg = tid & 31, kg = tid >> 5;
    int j0 = jg * 4;

    float mx[4] = {-3.4e38f, -3.4e38f, -3.4e38f, -3.4e38f};
    for (int t = 0; t < 16; t++) {
        int r = rb * 128 + kg + 8 * t;
        const float* hr = g_h3 + ((size_t)b*NS2 + r) * 256;
        float4 acc = make_float4(0.f, 0.f, 0.f, 0.f);
        for (int i = 0; i < 256; i++) {
            float f = hr[i];
            float4 wv = *(const float4*)&w3b[(size_t)i*1024 + cb*128 + j0];
            acc.x=fmaf(f,wv.x,acc.x); acc.y=fmaf(f,wv.y,acc.y);
            acc.z=fmaf(f,wv.z,acc.z); acc.w=fmaf(f,wv.w,acc.w);
        }
        mx[0]=fmaxf(mx[0],acc.x); mx[1]=fmaxf(mx[1],acc.y);
        mx[2]=fmaxf(mx[2],acc.z); mx[3]=fmaxf(mx[3],acc.w);
    }
#pragma unroll
    for (int q = 0; q < 4; q++) s_red[kg*128 + j0 + q] = mx[q];
    __syncthreads();
    if (tid < 32) {
        int j = tid * 4;
#pragma unroll
        for (int q = 0; q < 4; q++) {
            float v = s_red[j+q];
            for (int k = 1; k < 8; k++) v = fmaxf(v, s_red[k*128 + j + q]);
            g_part[(((size_t)b*8 + cb)*4 + rb)*128 + j + q] = v;
        }
    }
}

__global__ __launch_bounds__(1024) void fin_kernel(
    const float* __restrict__ b3b, float* __restrict__ out)
{
    int c = threadIdx.x, b = blockIdx.x;
    int cb = c >> 7, j = c & 127;
    float v = -3.4e38f;
    for (int rb = 0; rb < 4; rb++)
        v = fmaxf(v, g_part[(((size_t)b*8 + cb)*4 + rb)*128 + j]);
    out[(size_t)b*1024 + c] = __fadd_rn(v, b3b[c]);
}

// ---------------- launcher: kernel launches ONLY --------------------------
extern "C" void kernel_launch(void* const* d_in, const int* in_sizes, int n_in,
                              void* d_out, int out_size)
{
    const float* pos = (const float*)d_in[0];
    const float* w1a = (const float*)d_in[1];
    const float* b1a = (const float*)d_in[2];
    const float* w1b = (const float*)d_in[3];
    const float* b1b = (const float*)d_in[4];
    const float* w2a = (const float*)d_in[5];
    const float* b2a = (const float*)d_in[6];
    const float* w2b = (const float*)d_in[7];
    const float* b2b = (const float*)d_in[8];
    const float* w3a = (const float*)d_in[9];
    const float* b3a = (const float*)d_in[10];
    const float* w3b = (const float*)d_in[11];
    const float* b3b = (const float*)d_in[12];
    float* out = (float*)d_out;

    fps1_kernel<<<BATCH, 256>>>(pos);
    fps2_bq1_kernel<<<BATCH + BATCH*NS1, 256>>>(pos);
    bq2_mlp1_kernel<<<BATCH*NS2 + BATCH*NS1, 256>>>(pos, w1a, b1a, w1b, b1b);
    mlp2_kernel<<<BATCH*NS2, 256>>>(w2a, b2a, w2b, b2b);
    mlp3a_kernel<<<BATCH*32, 256>>>(w3a, b3a);
    mlp3b_kernel<<<dim3(4, 8, BATCH), 256>>>(w3b);
    fin_kernel<<<BATCH, 1024>>>(b3b, out);
    (void)in_sizes; (void)n_in; (void)out_size;
}